// round 14
// baseline (speedup 1.0000x reference)
#include <cuda_runtime.h>
#include <cuda_fp16.h>
#include <math.h>
#include <stdint.h>

#define NTOK 16384
#define H1D 256
#define TT 20
#define OFF_COORD 128
#define OFF_DIH   1628
#define OFF_CHAIN 1667

typedef unsigned short u16;
typedef unsigned int   u32;

// ---------------- scratch (static device globals; no allocation) ----------------
__device__ float g_tabA[TT * H1D];
__device__ float g_tabC[10 * H1D];
__device__ int g_cnt[TT];
__device__ int g_off[TT + 1];
__device__ int g_perm[NTOK];
__device__ int g_bhist[32 * TT];
__device__ int g_base[32 * TT];
__device__ int g_tiles[320];
__device__ int g_ntiles;
// pre-converted weights (single fp16), transposed to [n][k]
__device__ u16 g_w1t[TT * 256 * 128];
__device__ u16 g_w2t[128 * 256];
__device__ u16 g_w3t[128 * 128];
__device__ u16 g_w4t[128 * 128];

__constant__ float c_freq[6] = {1.0f, 2.0f, 3.0f, 1.0f, 0.5f, 1.0f / 3.0f};

// ---------------- helpers ----------------
__device__ __forceinline__ u32 smem_u32(const void* p) {
    u32 a;
    asm("{ .reg .u64 t; cvta.to.shared.u64 t, %1; cvt.u32.u64 %0, t; }" : "=r"(a) : "l"(p));
    return a;
}
__device__ __forceinline__ void split1h(float x, u32& h, u32& l) {
    __half hb = __float2half_rn(x);
    h = (u32)__half_as_ushort(hb);
    l = (u32)__half_as_ushort(__float2half_rn(x - __half2float(hb)));
}
// swizzled byte offset of 16B chunk c8 (0..15) in row r (rows of 128 fp16 = 256B)
__device__ __forceinline__ u32 swoff(int r, int c8) {
    return (u32)r * 256u + ((((u32)c8) & 8u) | ((((u32)c8) ^ (u32)r) & 7u)) * 16u;
}
__device__ __forceinline__ void ldsm_x4(u32 addr, u32 (&r)[4]) {
    asm volatile("ldmatrix.sync.aligned.m8n8.x4.shared.b16 {%0,%1,%2,%3}, [%4];"
        : "=r"(r[0]), "=r"(r[1]), "=r"(r[2]), "=r"(r[3]) : "r"(addr));
}
__device__ __forceinline__ void mma_f16(float (&d)[4], const u32 (&a)[4], u32 b0, u32 b1) {
    asm volatile("mma.sync.aligned.m16n8k16.row.col.f32.f16.f16.f32 "
        "{%0,%1,%2,%3}, {%4,%5,%6,%7}, {%8,%9}, {%0,%1,%2,%3};"
        : "+f"(d[0]), "+f"(d[1]), "+f"(d[2]), "+f"(d[3])
        : "r"(a[0]), "r"(a[1]), "r"(a[2]), "r"(a[3]), "r"(b0), "r"(b1));
}
__device__ __forceinline__ void cpa16(u32 s, const void* g) {
    asm volatile("cp.async.cg.shared.global [%0], [%1], 16;" :: "r"(s), "l"(g) : "memory");
}
#define CP_COMMIT() asm volatile("cp.async.commit_group;" ::: "memory")
#define CP_WAIT0()  asm volatile("cp.async.wait_group 0;" ::: "memory")

// 64x128x128 CTA GEMM piece: warp tile 32x32, fp16 2-term (A hi/lo, B single)
// A region: 64 rows (hi at +0, lo at +16384). B region: 128 rows.
__device__ __forceinline__ void wg32(u32 Ahi, u32 Bs,
                                     int m0w, int n0w, int lane,
                                     float (&acc)[2][4][4]) {
    int arow = (lane & 7) + ((lane >> 3) & 1) * 8;
    int akoff8 = (lane >> 4);
    int brow = (lane & 7) + ((lane >> 4) & 1) * 8;
    int bkoff8 = ((lane >> 3) & 1);
#pragma unroll
    for (int kc = 0; kc < 8; kc++) {
        u32 aH[2][4], aL[2][4], bS[2][4];
#pragma unroll
        for (int mi = 0; mi < 2; mi++) {
            u32 off = swoff(m0w + mi * 16 + arow, kc * 2 + akoff8);
            ldsm_x4(Ahi + off, aH[mi]);
            ldsm_x4(Ahi + 16384 + off, aL[mi]);
        }
#pragma unroll
        for (int np = 0; np < 2; np++) {
            u32 off = swoff(n0w + np * 16 + brow, kc * 2 + bkoff8);
            ldsm_x4(Bs + off, bS[np]);
        }
#pragma unroll
        for (int mi = 0; mi < 2; mi++)
#pragma unroll
            for (int nj = 0; nj < 4; nj++)
                mma_f16(acc[mi][nj], aH[mi],
                        bS[nj >> 1][(nj & 1) * 2], bS[nj >> 1][(nj & 1) * 2 + 1]);
#pragma unroll
        for (int mi = 0; mi < 2; mi++)
#pragma unroll
            for (int nj = 0; nj < 4; nj++)
                mma_f16(acc[mi][nj], aL[mi],
                        bS[nj >> 1][(nj & 1) * 2], bS[nj >> 1][(nj & 1) * 2 + 1]);
    }
}

// ---------------- fused prep kernel ----------------
__global__ void __launch_bounds__(256)
k_prep(const int* __restrict__ seq, const float* __restrict__ aa_emb,
       const float* __restrict__ chain_emb, const float* __restrict__ W1,
       const float* __restrict__ b1, const float* __restrict__ W2,
       const float* __restrict__ W3, const float* __restrict__ W4) {
    int b = blockIdx.x, tid = threadIdx.x;
    if (b < 32) {
        __shared__ int h[TT];
        if (tid < TT) h[tid] = 0;
        __syncthreads();
        int base = b * 512;
        atomicAdd(&h[seq[base + tid]], 1);
        atomicAdd(&h[seq[base + 256 + tid]], 1);
        __syncthreads();
        if (tid < TT) g_bhist[b * TT + tid] = h[tid];
        return;
    }
    if (b < 62) {
        int r = b - 32, j = tid;
        float acc = 0.f;
        if (r < TT) {
            const float* e = aa_emb + r * 128;
#pragma unroll 8
            for (int k = 0; k < 128; k++) acc += e[k] * W1[k * H1D + j];
            g_tabA[r * H1D + j] = acc + b1[j];
        } else {
            int c = r - TT;
            if (c != 0) {
                const float* e = chain_emb + c * 128;
#pragma unroll 8
                for (int k = 0; k < 128; k++) acc += e[k] * W1[(OFF_CHAIN + k) * H1D + j];
            }
            g_tabC[c * H1D + j] = acc;
        }
        return;
    }
    __shared__ float s[128][33];
    const float* src;
    u16* dh;
    int Kd, n0glob, kskip = 0, srcN, srcRow0 = 0;
    bool w1 = false;
    int t = 0;
    if (b < 222) {
        int bb = b - 62;
        t = bb >> 3;
        int nb = bb & 7;
        w1 = true;
        src = W1; srcN = 256; n0glob = nb * 32;
        dh = g_w1t + (size_t)t * 256 * 128;
        Kd = 128;
    } else if (b < 230) {
        int bb = b - 222;
        int nb = bb & 3, kb = bb >> 2;
        src = W2; srcN = 128; n0glob = nb * 32; srcRow0 = kb * 128; kskip = kb * 128;
        dh = g_w2t; Kd = 256;
    } else if (b < 234) {
        int nb = b - 230;
        src = W3; srcN = 128; n0glob = nb * 32;
        dh = g_w3t; Kd = 128;
    } else {
        int nb = b - 234;
        src = W4; srcN = 128; n0glob = nb * 32;
        dh = g_w4t; Kd = 128;
    }
#pragma unroll
    for (int it = 0; it < 16; it++) {
        int idx = tid + it * 256;
        int k = idx >> 5, nn = idx & 31;
        float v;
        if (w1) {
            if (k < 75) v = src[(size_t)(OFF_COORD + t * 75 + k) * srcN + n0glob + nn];
            else if (k < 114) v = src[(size_t)(OFF_DIH + k - 75) * srcN + n0glob + nn];
            else v = 0.f;
        } else {
            v = src[(size_t)(srcRow0 + k) * srcN + n0glob + nn];
        }
        s[k][nn] = v;
    }
    __syncthreads();
#pragma unroll
    for (int it = 0; it < 8; it++) {
        int idx = tid + it * 256;
        int n = idx >> 6, kk = (idx & 63) * 2;
        u32 h0 = (u32)__half_as_ushort(__float2half_rn(s[kk][n]));
        u32 h1 = (u32)__half_as_ushort(__float2half_rn(s[kk + 1][n]));
        size_t o = (size_t)(n0glob + n) * Kd + kskip + kk;
        *(u32*)(dh + o) = h0 | (h1 << 16);
    }
}

// ---------------- scan + tile table (64-token tiles) ----------------
__global__ void k_scan2() {
    __shared__ int sh[32][TT];
    __shared__ int spref[32][TT];
    __shared__ int scnt[TT];
    __shared__ int soff[TT + 1];
    int tid = threadIdx.x;
    if (tid < 640) sh[tid / TT][tid % TT] = g_bhist[tid];
    __syncthreads();
    if (tid < TT) {
        int run = 0;
#pragma unroll
        for (int b = 0; b < 32; b++) { spref[b][tid] = run; run += sh[b][tid]; }
        scnt[tid] = run;
    }
    __syncthreads();
    if (tid == 0) {
        int o = 0;
        for (int t = 0; t < TT; t++) { soff[t] = o; o += scnt[t]; }
        soff[TT] = o;
        int idx = 0;
        for (int t = 0; t < TT; t++)
            for (int tl = 0; tl * 64 < scnt[t]; tl++) g_tiles[idx++] = (t << 9) | tl;
        g_ntiles = idx;
    }
    __syncthreads();
    if (tid < TT) { g_cnt[tid] = scnt[tid]; g_off[tid] = soff[tid]; }
    if (tid == 0) g_off[TT] = soff[TT];
    if (tid < 640) g_base[tid] = soff[tid % TT] + spref[tid / TT][tid % TT];
}

// ---------------- scatter ----------------
__global__ void __launch_bounds__(512)
k_scatter2(const int* __restrict__ seq) {
    __shared__ int cur[TT];
    int tid = threadIdx.x;
    if (tid < TT) cur[tid] = g_base[blockIdx.x * TT + tid];
    __syncthreads();
    int i = blockIdx.x * 512 + tid;
    int t = seq[i];
    int pos = atomicAdd(&cur[t], 1);
    g_perm[pos] = i;
}

// ---------------- fused main kernel (M=64 tiles, 256 threads, 2 CTAs/SM) ----------------
// RA, RB: 64-row activation regions (hi +0, lo +16384), 32KB each
// RW: single 128-row weight region, 32KB (reloaded per phase)
// tabC read directly from global (L1-resident 10KB) to keep smem under half-SM.
#define RA  0
#define RB  32768
#define RW  65536
#define EX_TA   98304
#define EX_B2   99328
#define EX_B3   99840
#define EX_B4   100352
#define EX_TOK  100864
#define EX_CH   101120
#define SMEM_MAIN 101376

__global__ void __launch_bounds__(256, 2)
k_main(const float* __restrict__ xyz, const float* __restrict__ dih,
       const int* __restrict__ cidx, const float* __restrict__ ori,
       const float* __restrict__ b2, const float* __restrict__ b3,
       const float* __restrict__ b4, float* __restrict__ out) {
    extern __shared__ char smem[];
    u32 sb = smem_u32(smem);
    int tid = threadIdx.x, wid = tid >> 5, lane = tid & 31;
    int* toks_s = (int*)(smem + EX_TOK);
    int* ch_s = (int*)(smem + EX_CH);
    float* tabA_s = (float*)(smem + EX_TA);
    float* bs2 = (float*)(smem + EX_B2);
    float* bs3 = (float*)(smem + EX_B3);
    float* bs4 = (float*)(smem + EX_B4);

    if (tid < 128) {
        bs2[tid] = b2[tid];
        bs3[tid] = b3[tid];
        bs4[tid] = b4[tid];
    }

    int m0w = (wid & 1) * 32;      // 2 m-groups
    int n0w = (wid >> 1) * 32;     // 4 n-groups
    int r_fill = tid & 127;
    int c0_fill = (tid >> 7) * 8;  // 2 threads per weight row, 8 chunks each
    int nt = g_ntiles;

#define FILL_W(SRC, STRIDE, KOFF) do { \
        const uint4* _s = (const uint4*)((SRC) + (size_t)r_fill * (STRIDE) + (KOFF)); \
        _Pragma("unroll") \
        for (int i = 0; i < 8; i++) { \
            u32 o = swoff(r_fill, c0_fill + i); \
            cpa16(sb + RW + o, _s + c0_fill + i); \
        } \
        CP_COMMIT(); \
    } while (0)

#define ZERO_ACC() do { \
        _Pragma("unroll") for (int _a = 0; _a < 2; _a++) \
        _Pragma("unroll") for (int _b = 0; _b < 4; _b++) \
        _Pragma("unroll") for (int _c = 0; _c < 4; _c++) acc[_a][_b][_c] = 0.f; \
    } while (0)

// epilogue into 64-row region (hi +0, lo +16384)
#define EPI_SMEM(DST, EXPR) do { \
        _Pragma("unroll") \
        for (int mi = 0; mi < 2; mi++) \
        _Pragma("unroll") \
        for (int nj = 0; nj < 4; nj++) { \
            int c_l = n0w + nj * 8 + (lane & 3) * 2; \
            _Pragma("unroll") \
            for (int hh = 0; hh < 2; hh++) { \
                int r_l = m0w + mi * 16 + (lane >> 2) + hh * 8; \
                float v0x = acc[mi][nj][2 * hh], v1x = acc[mi][nj][2 * hh + 1]; \
                float v0 = (EXPR(v0x, r_l, c_l)); \
                float v1 = (EXPR(v1x, r_l, (c_l + 1))); \
                u32 h0, l0, h1, l1; \
                split1h(v0, h0, l0); split1h(v1, h1, l1); \
                u32 o = swoff(r_l, c_l >> 3) + (c_l & 7) * 2; \
                *(u32*)&smem[(DST) + o] = h0 | (h1 << 16); \
                *(u32*)&smem[(DST) + 16384 + o] = l0 | (l1 << 16); \
            } \
        } \
    } while (0)

    for (int w = blockIdx.x; w < nt; w += gridDim.x) {
        int e = g_tiles[w];
        int type = e >> 9;
        int tile = e & 511;
        int cnt = g_cnt[type];
        int start = g_off[type] + tile * 64;
        int n = min(64, cnt - tile * 64);

        __syncthreads();   // S0: previous tile fully done (RA/RB/RW/toks free)
        if (tid < 64) {
            int tok = (tid < n) ? g_perm[start + tid] : -1;
            toks_s[tid] = tok;
            ch_s[tid] = (tok >= 0) ? cidx[tok] : 0;
        }
        for (int i = tid; i < 256; i += 256) tabA_s[i] = g_tabA[type * H1D + i];
        // C1: W1a -> RW (under feature phase)
        FILL_W(g_w1t + (size_t)type * 256 * 128, 128, 0);
        __syncthreads();   // S1: toks visible

        // ---- features -> RA : warp w owns tokens w*8..w*8+7, lanes sweep k ----
        {
#pragma unroll 1
            for (int ti = 0; ti < 8; ti++) {
                int t = wid * 8 + ti;
                int tok = toks_s[t];
                const float* xb = xyz + (size_t)(tok < 0 ? 0 : tok) * 75;
                const float* ob = ori + (size_t)(tok < 0 ? 0 : tok) * 9;
                float cax = 0.f, cay = 0.f, caz = 0.f, d0 = 0.f, d1 = 0.f, d2 = 0.f;
                if (tok >= 0) {
                    cax = xb[3]; cay = xb[4]; caz = xb[5];
                    d0 = dih[(size_t)tok * 3]; d1 = dih[(size_t)tok * 3 + 1]; d2 = dih[(size_t)tok * 3 + 2];
                }
#pragma unroll
                for (int i = 0; i < 4; i++) {
                    int k = i * 32 + lane;
                    float v = 0.f;
                    if (tok >= 0) {
                        if (k < 75) {
                            int a = k / 3, c = k - a * 3;
                            float r0 = xb[a * 3 + 0] - cax;
                            float r1 = xb[a * 3 + 1] - cay;
                            float r2 = xb[a * 3 + 2] - caz;
                            v = ob[c] * r0 + ob[3 + c] * r1 + ob[6 + c] * r2;
                        } else if (k < 114) {
                            int kd = k - 75;
                            int dm = kd / 13, q = kd - dm * 13;
                            float x = (dm == 0) ? d0 : (dm == 1) ? d1 : d2;
                            if (q == 0) v = x;
                            else if (q <= 6) v = __sinf(c_freq[q - 1] * x);
                            else v = __cosf(c_freq[q - 7] * x);
                        }
                    }
                    u32 h, l;
                    split1h(v, h, l);
                    u32 o = swoff(t, k >> 3) + (k & 7) * 2;
                    *(u16*)&smem[RA + o] = (u16)h;
                    *(u16*)&smem[RA + 16384 + o] = (u16)l;
                }
            }
        }
        CP_WAIT0();
        __syncthreads();   // S2: features + W1a visible

        float acc[2][4][4];

        // ---- G1: L1 half0 = feat(RA) x W1a(RW) ----
        ZERO_ACC();
        wg32(sb + RA, sb + RW, m0w, n0w, lane, acc);
        __syncthreads();   // S3: RW free

        // C2: W1b -> RW ; epi0 (h1c0) -> RB
        FILL_W(g_w1t + (size_t)(type * 256 + 128) * 128, 128, 0);
#define L1EXPR0(v, r, c) fmaxf((v) + tabA_s[(c)] + g_tabC[ch_s[(r)] * 256 + (c)], 0.f)
        EPI_SMEM(RB, L1EXPR0);
        CP_WAIT0();
        __syncthreads();   // S4: W1b + h1c0 visible

        // ---- G2: L1 half1 = feat(RA) x W1b(RW) ----
        ZERO_ACC();
        wg32(sb + RA, sb + RW, m0w, n0w, lane, acc);
        __syncthreads();   // S5: RW free, RA (feat) dead after this gemm

        // C3: W2a -> RW ; epi1 (h1c1) -> RA
        FILL_W(g_w2t, 256, 0);
#define L1EXPR1(v, r, c) fmaxf((v) + tabA_s[128 + (c)] + g_tabC[ch_s[(r)] * 256 + 128 + (c)], 0.f)
        EPI_SMEM(RA, L1EXPR1);
        CP_WAIT0();
        __syncthreads();   // S6: W2a + h1c1 visible

        // ---- G3: L2 chunk0 = h1c0(RB) x W2a(RW) ----
        ZERO_ACC();
        wg32(sb + RB, sb + RW, m0w, n0w, lane, acc);
        __syncthreads();   // S7: RW free

        // C4: W2b -> RW (exposed; co-resident CTA covers)
        FILL_W(g_w2t, 256, 128);
        CP_WAIT0();
        __syncthreads();   // S8: W2b visible

        // ---- G4: L2 chunk1 accumulate = h1c1(RA) x W2b(RW) ----
        wg32(sb + RA, sb + RW, m0w, n0w, lane, acc);
        __syncthreads();   // S9: RW free, RB free (read in G3)

        // C5: W3 -> RW ; epi2 (h2) -> RB
        FILL_W(g_w3t, 128, 0);
#define ACTEXPR2(v, r, c) fmaxf((v) + bs2[(c)], 0.f)
        EPI_SMEM(RB, ACTEXPR2);
        CP_WAIT0();
        __syncthreads();   // S10: W3 + h2 visible

        // ---- G5: L3 = h2(RB) x W3(RW) ----
        ZERO_ACC();
        wg32(sb + RB, sb + RW, m0w, n0w, lane, acc);
        __syncthreads();   // S11: RW free; RA (h1c1) dead since G4

        // C6: W4 -> RW ; epi3 (h3) -> RA
        FILL_W(g_w4t, 128, 0);
#define ACTEXPR3(v, r, c) fmaxf((v) + bs3[(c)], 0.f)
        EPI_SMEM(RA, ACTEXPR3);
        CP_WAIT0();
        __syncthreads();   // S12: W4 + h3 visible

        // ---- G6: L4 = h3(RA) x W4(RW) ; final epilogue -> gmem ----
        ZERO_ACC();
        wg32(sb + RA, sb + RW, m0w, n0w, lane, acc);

#pragma unroll
        for (int mi = 0; mi < 2; mi++)
#pragma unroll
            for (int nj = 0; nj < 4; nj++) {
                int c_l = n0w + nj * 8 + (lane & 3) * 2;
                float bb0 = bs4[c_l], bb1 = bs4[c_l + 1];
#pragma unroll
                for (int hh = 0; hh < 2; hh++) {
                    int r_l = m0w + mi * 16 + (lane >> 2) + hh * 8;
                    int tok = toks_s[r_l];
                    if (tok >= 0) {
                        float2 v;
                        v.x = acc[mi][nj][2 * hh] + bb0;
                        v.y = acc[mi][nj][2 * hh + 1] + bb1;
                        *(float2*)(out + (size_t)tok * 128 + c_l) = v;
                    }
                }
            }
    }
}

// ---------------- host ----------------
extern "C" void kernel_launch(void* const* d_in, const int* in_sizes, int n_in,
                              void* d_out, int out_size) {
    const int* seq = (const int*)d_in[0];
    const float* xyz = (const float*)d_in[1];
    const float* dih = (const float*)d_in[2];
    const int* cidx = (const int*)d_in[3];
    const float* ori = (const float*)d_in[4];
    const float* aa_emb = (const float*)d_in[6];
    const float* chain_emb = (const float*)d_in[7];
    const float* W1 = (const float*)d_in[8];
    const float* b1 = (const float*)d_in[9];
    const float* W2 = (const float*)d_in[10];
    const float* b2 = (const float*)d_in[11];
    const float* W3 = (const float*)d_in[12];
    const float* b3 = (const float*)d_in[13];
    const float* W4 = (const float*)d_in[14];
    const float* b4 = (const float*)d_in[15];
    float* out = (float*)d_out;

    cudaFuncSetAttribute(k_main, cudaFuncAttributeMaxDynamicSharedMemorySize, SMEM_MAIN);
    cudaFuncSetAttribute(k_main, cudaFuncAttributePreferredSharedMemoryCarveout, 100);

    k_prep<<<238, 256>>>(seq, aa_emb, chain_emb, W1, b1, W2, W3, W4);
    k_scan2<<<1, 640>>>();
    k_scatter2<<<32, 512>>>(seq);
    k_main<<<296, 256, SMEM_MAIN>>>(xyz, dih, cidx, ori, b2, b3, b4, out);
}

// round 16
// speedup vs baseline: 1.3778x; 1.3778x over previous
#include <cuda_runtime.h>
#include <cuda_fp16.h>
#include <math.h>
#include <stdint.h>

#define NTOK 16384
#define H1D 256
#define TT 20
#define OFF_COORD 128
#define OFF_DIH   1628
#define OFF_CHAIN 1667

typedef unsigned short u16;
typedef unsigned int   u32;

// ---------------- scratch (static device globals; no allocation) ----------------
__device__ float g_tabA[TT * H1D];
__device__ float g_tabC[10 * H1D];
__device__ int g_cnt[TT];
__device__ int g_off[TT + 1];
__device__ int g_perm[NTOK];
__device__ int g_bhist[32 * TT];
__device__ int g_tiles[256];
__device__ int g_ntiles;
// pre-converted weights (single fp16), transposed to [n][k]
__device__ u16 g_w1t[TT * 256 * 128];
__device__ u16 g_w2t[128 * 256];
__device__ u16 g_w3t[128 * 128];
__device__ u16 g_w4t[128 * 128];

__constant__ float c_freq[6] = {1.0f, 2.0f, 3.0f, 1.0f, 0.5f, 1.0f / 3.0f};

// ---------------- helpers ----------------
__device__ __forceinline__ u32 smem_u32(const void* p) {
    u32 a;
    asm("{ .reg .u64 t; cvta.to.shared.u64 t, %1; cvt.u32.u64 %0, t; }" : "=r"(a) : "l"(p));
    return a;
}
__device__ __forceinline__ u32 f2h(float x) {
    return (u32)__half_as_ushort(__float2half_rn(x));
}
// swizzled byte offset of 16B chunk c8 (0..15) in row r (rows of 128 fp16 = 256B)
__device__ __forceinline__ u32 swoff(int r, int c8) {
    return (u32)r * 256u + ((((u32)c8) & 8u) | ((((u32)c8) ^ (u32)r) & 7u)) * 16u;
}
__device__ __forceinline__ void ldsm_x4(u32 addr, u32 (&r)[4]) {
    asm volatile("ldmatrix.sync.aligned.m8n8.x4.shared.b16 {%0,%1,%2,%3}, [%4];"
        : "=r"(r[0]), "=r"(r[1]), "=r"(r[2]), "=r"(r[3]) : "r"(addr));
}
__device__ __forceinline__ void mma_f16(float (&d)[4], const u32 (&a)[4], u32 b0, u32 b1) {
    asm volatile("mma.sync.aligned.m16n8k16.row.col.f32.f16.f16.f32 "
        "{%0,%1,%2,%3}, {%4,%5,%6,%7}, {%8,%9}, {%0,%1,%2,%3};"
        : "+f"(d[0]), "+f"(d[1]), "+f"(d[2]), "+f"(d[3])
        : "r"(a[0]), "r"(a[1]), "r"(a[2]), "r"(a[3]), "r"(b0), "r"(b1));
}
__device__ __forceinline__ void cpa16(u32 s, const void* g) {
    asm volatile("cp.async.cg.shared.global [%0], [%1], 16;" :: "r"(s), "l"(g) : "memory");
}
#define CP_COMMIT() asm volatile("cp.async.commit_group;" ::: "memory")
#define CP_WAIT0()  asm volatile("cp.async.wait_group 0;" ::: "memory")

// single-term fp16: warp tile 32x32 over N=128
__device__ __forceinline__ void wg32s(u32 As, u32 Bs,
                                      int m0w, int n0w, int lane,
                                      float (&acc)[2][8][4]) {
    int arow = (lane & 7) + ((lane >> 3) & 1) * 8;
    int akoff8 = (lane >> 4);
    int brow = (lane & 7) + ((lane >> 4) & 1) * 8;
    int bkoff8 = ((lane >> 3) & 1);
#pragma unroll
    for (int kc = 0; kc < 8; kc++) {
        u32 aS[2][4], bS[2][4];
#pragma unroll
        for (int mi = 0; mi < 2; mi++) {
            u32 off = swoff(m0w + mi * 16 + arow, kc * 2 + akoff8);
            ldsm_x4(As + off, aS[mi]);
        }
#pragma unroll
        for (int np = 0; np < 2; np++) {
            u32 off = swoff(n0w + np * 16 + brow, kc * 2 + bkoff8);
            ldsm_x4(Bs + off, bS[np]);
        }
#pragma unroll
        for (int mi = 0; mi < 2; mi++)
#pragma unroll
            for (int nj = 0; nj < 4; nj++)
                mma_f16(acc[mi][nj], aS[mi],
                        bS[nj >> 1][(nj & 1) * 2], bS[nj >> 1][(nj & 1) * 2 + 1]);
    }
}

// single-term fp16: warp tile 32x64 (nj 0..7), B local region + local n offset
__device__ __forceinline__ void wg64s(u32 As, u32 Bs, int n0loc,
                                      int m0w, int lane,
                                      float (&acc)[2][8][4]) {
    int arow = (lane & 7) + ((lane >> 3) & 1) * 8;
    int akoff8 = (lane >> 4);
    int brow = (lane & 7) + ((lane >> 4) & 1) * 8;
    int bkoff8 = ((lane >> 3) & 1);
#pragma unroll
    for (int kc = 0; kc < 8; kc++) {
        u32 aS[2][4], bS[4][4];
#pragma unroll
        for (int mi = 0; mi < 2; mi++) {
            u32 off = swoff(m0w + mi * 16 + arow, kc * 2 + akoff8);
            ldsm_x4(As + off, aS[mi]);
        }
#pragma unroll
        for (int np = 0; np < 4; np++) {
            u32 off = swoff(n0loc + np * 16 + brow, kc * 2 + bkoff8);
            ldsm_x4(Bs + off, bS[np]);
        }
#pragma unroll
        for (int mi = 0; mi < 2; mi++)
#pragma unroll
            for (int nj = 0; nj < 8; nj++)
                mma_f16(acc[mi][nj], aS[mi],
                        bS[nj >> 1][(nj & 1) * 2], bS[nj >> 1][(nj & 1) * 2 + 1]);
    }
}

// ---------------- fused prep kernel ----------------
__global__ void __launch_bounds__(256)
k_prep(const int* __restrict__ seq, const float* __restrict__ aa_emb,
       const float* __restrict__ chain_emb, const float* __restrict__ W1,
       const float* __restrict__ b1, const float* __restrict__ W2,
       const float* __restrict__ W3, const float* __restrict__ W4) {
    int b = blockIdx.x, tid = threadIdx.x;
    if (b < 32) {
        __shared__ int h[TT];
        if (tid < TT) h[tid] = 0;
        __syncthreads();
        int base = b * 512;
        atomicAdd(&h[seq[base + tid]], 1);
        atomicAdd(&h[seq[base + 256 + tid]], 1);
        __syncthreads();
        if (tid < TT) g_bhist[b * TT + tid] = h[tid];
        return;
    }
    if (b < 62) {
        int r = b - 32, j = tid;
        float acc = 0.f;
        if (r < TT) {
            const float* e = aa_emb + r * 128;
#pragma unroll 8
            for (int k = 0; k < 128; k++) acc += e[k] * W1[k * H1D + j];
            g_tabA[r * H1D + j] = acc + b1[j];
        } else {
            int c = r - TT;
            if (c != 0) {
                const float* e = chain_emb + c * 128;
#pragma unroll 8
                for (int k = 0; k < 128; k++) acc += e[k] * W1[(OFF_CHAIN + k) * H1D + j];
            }
            g_tabC[c * H1D + j] = acc;
        }
        return;
    }
    __shared__ float s[128][33];
    const float* src;
    u16* dh;
    int Kd, n0glob, kskip = 0, srcN, srcRow0 = 0;
    bool w1 = false;
    int t = 0;
    if (b < 222) {
        int bb = b - 62;
        t = bb >> 3;
        int nb = bb & 7;
        w1 = true;
        src = W1; srcN = 256; n0glob = nb * 32;
        dh = g_w1t + (size_t)t * 256 * 128;
        Kd = 128;
    } else if (b < 230) {
        int bb = b - 222;
        int nb = bb & 3, kb = bb >> 2;
        src = W2; srcN = 128; n0glob = nb * 32; srcRow0 = kb * 128; kskip = kb * 128;
        dh = g_w2t; Kd = 256;
    } else if (b < 234) {
        int nb = b - 230;
        src = W3; srcN = 128; n0glob = nb * 32;
        dh = g_w3t; Kd = 128;
    } else {
        int nb = b - 234;
        src = W4; srcN = 128; n0glob = nb * 32;
        dh = g_w4t; Kd = 128;
    }
#pragma unroll
    for (int it = 0; it < 16; it++) {
        int idx = tid + it * 256;
        int k = idx >> 5, nn = idx & 31;
        float v;
        if (w1) {
            if (k < 75) v = src[(size_t)(OFF_COORD + t * 75 + k) * srcN + n0glob + nn];
            else if (k < 114) v = src[(size_t)(OFF_DIH + k - 75) * srcN + n0glob + nn];
            else v = 0.f;
        } else {
            v = src[(size_t)(srcRow0 + k) * srcN + n0glob + nn];
        }
        s[k][nn] = v;
    }
    __syncthreads();
#pragma unroll
    for (int it = 0; it < 8; it++) {
        int idx = tid + it * 256;
        int n = idx >> 6, kk = (idx & 63) * 2;
        u32 h0 = f2h(s[kk][n]);
        u32 h1 = f2h(s[kk + 1][n]);
        size_t o = (size_t)(n0glob + n) * Kd + kskip + kk;
        *(u32*)(dh + o) = h0 | (h1 << 16);
    }
}

// ---------------- scatter (scan folded in; block 0 publishes tile table) ----------------
__global__ void __launch_bounds__(512)
k_scatter2(const int* __restrict__ seq) {
    __shared__ int bh[32][TT];
    __shared__ int cnt[TT];
    __shared__ int off[TT + 1];
    __shared__ int cur[TT];
    __shared__ int pref[TT];
    int tid = threadIdx.x, b = blockIdx.x;
    for (int i = tid; i < 32 * TT; i += 512) bh[i / TT][i % TT] = g_bhist[i];
    __syncthreads();
    if (tid < TT) {
        int run = 0, mypref = 0;
#pragma unroll
        for (int s = 0; s < 32; s++) {
            if (s == b) mypref = run;
            run += bh[s][tid];
        }
        cnt[tid] = run;
        pref[tid] = mypref;
    }
    __syncthreads();
    if (tid == 0) {
        int o = 0;
        for (int t = 0; t < TT; t++) { off[t] = o; o += cnt[t]; }
        off[TT] = o;
    }
    __syncthreads();
    if (tid < TT) cur[tid] = off[tid] + pref[tid];
    if (b == 0) {
        if (tid < TT) { g_cnt[tid] = cnt[tid]; g_off[tid] = off[tid]; }
        if (tid == 0) {
            g_off[TT] = off[TT];
            int idx = 0;
            for (int t = 0; t < TT; t++)
                for (int tl = 0; tl * 128 < cnt[t]; tl++) g_tiles[idx++] = (t << 8) | tl;
            g_ntiles = idx;
        }
    }
    __syncthreads();
    int i = b * 512 + tid;
    int t = seq[i];
    int pos = atomicAdd(&cur[t], 1);
    g_perm[pos] = i;
}

// ---------------- fused main kernel (single-term fp16, 128-token tiles) ----------------
// RA, RB: 32KB activation regions (single fp16). RW0, RW1: 32KB weight regions.
#define RA  0
#define RB  32768
#define RW0 65536
#define RW1 98304
#define EX_TA   131072
#define EX_TC   132096
#define EX_B2   142336
#define EX_B3   142848
#define EX_B4   143360
#define EX_TOK  143872
#define EX_CH   144384
#define SMEM_MAIN 144896

__global__ void __launch_bounds__(512, 1)
k_main(const float* __restrict__ xyz, const float* __restrict__ dih,
       const int* __restrict__ cidx, const float* __restrict__ ori,
       const float* __restrict__ b2, const float* __restrict__ b3,
       const float* __restrict__ b4, float* __restrict__ out) {
    extern __shared__ char smem[];
    u32 sb = smem_u32(smem);
    int tid = threadIdx.x, wid = tid >> 5, lane = tid & 31;
    int* toks_s = (int*)(smem + EX_TOK);
    int* ch_s = (int*)(smem + EX_CH);
    float* tabA_s = (float*)(smem + EX_TA);
    float* tabC_s = (float*)(smem + EX_TC);
    float* bs2 = (float*)(smem + EX_B2);
    float* bs3 = (float*)(smem + EX_B3);
    float* bs4 = (float*)(smem + EX_B4);

    if (tid < 128) {
        bs2[tid] = b2[tid];
        bs3[tid] = b3[tid];
        bs4[tid] = b4[tid];
    }
    for (int i = tid; i < 2560; i += 512) tabC_s[i] = g_tabC[i];

    int m0w = (wid & 3) * 32;
    int n0w64 = (wid >> 2) * 64;
    int n0w32 = (wid >> 2) * 32;
    int r_fill = tid & 127;
    int c0_fill = (tid >> 7) * 4;
    int nt = g_ntiles;

#define FILL_W(DST, SRC, STRIDE, KOFF) do { \
        const uint4* _s = (const uint4*)((SRC) + (size_t)r_fill * (STRIDE) + (KOFF)); \
        _Pragma("unroll") \
        for (int i = 0; i < 4; i++) { \
            u32 o = swoff(r_fill, c0_fill + i); \
            cpa16(sb + (DST) + o, _s + c0_fill + i); \
        } \
    } while (0)

#define ZERO_ACC8() do { \
        _Pragma("unroll") for (int _a = 0; _a < 2; _a++) \
        _Pragma("unroll") for (int _b = 0; _b < 8; _b++) \
        _Pragma("unroll") for (int _c = 0; _c < 4; _c++) acc[_a][_b][_c] = 0.f; \
    } while (0)

#define ZERO_ACC4() do { \
        _Pragma("unroll") for (int _a = 0; _a < 2; _a++) \
        _Pragma("unroll") for (int _b = 0; _b < 4; _b++) \
        _Pragma("unroll") for (int _c = 0; _c < 4; _c++) acc[_a][_b][_c] = 0.f; \
    } while (0)

// epilogue for N=128 phases (nj 0..3) into a single fp16 region
#define EPI_SMEM4(DST, EXPR) do { \
        _Pragma("unroll") \
        for (int mi = 0; mi < 2; mi++) \
        _Pragma("unroll") \
        for (int nj = 0; nj < 4; nj++) { \
            int c_l = n0w32 + nj * 8 + (lane & 3) * 2; \
            _Pragma("unroll") \
            for (int hh = 0; hh < 2; hh++) { \
                int r_l = m0w + mi * 16 + (lane >> 2) + hh * 8; \
                float v0 = (EXPR(acc[mi][nj][2 * hh], r_l, c_l)); \
                float v1 = (EXPR(acc[mi][nj][2 * hh + 1], r_l, (c_l + 1))); \
                u32 o = swoff(r_l, c_l >> 3) + (c_l & 7) * 2; \
                *(u32*)&smem[(DST) + o] = f2h(v0) | (f2h(v1) << 16); \
            } \
        } \
    } while (0)

    for (int w = blockIdx.x; w < nt; w += gridDim.x) {
        int e = g_tiles[w];
        int type = e >> 8;
        int tile = e & 255;
        int cnt = g_cnt[type];
        int start = g_off[type] + tile * 128;
        int n = min(128, cnt - tile * 128);

        __syncthreads();   // S0: previous tile fully done
        if (tid < 128) {
            int tok = (tid < n) ? g_perm[start + tid] : -1;
            toks_s[tid] = tok;
            ch_s[tid] = (tok >= 0) ? cidx[tok] : 0;
        }
        for (int i = tid; i < 256; i += 512) tabA_s[i] = g_tabA[type * H1D + i];
        // C1: W1a -> RW0, W1b -> RW1 (under feature phase)
        FILL_W(RW0, g_w1t + (size_t)type * 256 * 128, 128, 0);
        FILL_W(RW1, g_w1t + (size_t)(type * 256 + 128) * 128, 128, 0);
        CP_COMMIT();
        __syncthreads();   // S1: toks visible

        // ---- features -> RA (single fp16) ----
        {
#pragma unroll 1
            for (int ti = 0; ti < 8; ti++) {
                int t = wid * 8 + ti;
                int tok = toks_s[t];
                const float* xb = xyz + (size_t)(tok < 0 ? 0 : tok) * 75;
                const float* ob = ori + (size_t)(tok < 0 ? 0 : tok) * 9;
                float cax = 0.f, cay = 0.f, caz = 0.f, d0 = 0.f, d1 = 0.f, d2 = 0.f;
                if (tok >= 0) {
                    cax = xb[3]; cay = xb[4]; caz = xb[5];
                    d0 = dih[(size_t)tok * 3]; d1 = dih[(size_t)tok * 3 + 1]; d2 = dih[(size_t)tok * 3 + 2];
                }
#pragma unroll
                for (int i = 0; i < 4; i++) {
                    int k = i * 32 + lane;
                    float v = 0.f;
                    if (tok >= 0) {
                        if (k < 75) {
                            int a = k / 3, c = k - a * 3;
                            float r0 = xb[a * 3 + 0] - cax;
                            float r1 = xb[a * 3 + 1] - cay;
                            float r2 = xb[a * 3 + 2] - caz;
                            v = ob[c] * r0 + ob[3 + c] * r1 + ob[6 + c] * r2;
                        } else if (k < 114) {
                            int kd = k - 75;
                            int dm = kd / 13, q = kd - dm * 13;
                            float x = (dm == 0) ? d0 : (dm == 1) ? d1 : d2;
                            if (q == 0) v = x;
                            else if (q <= 6) v = __sinf(c_freq[q - 1] * x);
                            else v = __cosf(c_freq[q - 7] * x);
                        }
                    }
                    u32 o = swoff(t, k >> 3) + (k & 7) * 2;
                    *(u16*)&smem[RA + o] = (u16)f2h(v);
                }
            }
        }
        CP_WAIT0();
        __syncthreads();   // S2: features + W1 visible

        float acc[2][8][4];

        // ---- G12: L1 full N=256 = feat(RA) x [W1a(RW0) | W1b(RW1)] ----
        ZERO_ACC8();
        {
            u32 Bs = (n0w64 < 128) ? (sb + RW0) : (sb + RW1);
            wg64s(sb + RA, Bs, n0w64 & 127, m0w, lane, acc);
        }
        __syncthreads();   // S3: RW0/RW1/RB free; RA (feat) dead after epi writes

        // C2: W2a -> RW0, W2b -> RW1 (under epilogue)
        FILL_W(RW0, g_w2t, 256, 0);
        FILL_W(RW1, g_w2t, 256, 128);
        CP_COMMIT();

        // epi01: h1 cols<128 -> RB, cols>=128 -> RA
        {
            int dst = (n0w64 < 128) ? RB : RA;
#pragma unroll
            for (int mi = 0; mi < 2; mi++)
#pragma unroll
                for (int nj = 0; nj < 8; nj++) {
                    int c_g = n0w64 + nj * 8 + (lane & 3) * 2;
                    int c_l = c_g & 127;
#pragma unroll
                    for (int hh = 0; hh < 2; hh++) {
                        int r_l = m0w + mi * 16 + (lane >> 2) + hh * 8;
                        int ch = ch_s[r_l];
                        float v0 = fmaxf(acc[mi][nj][2 * hh] + tabA_s[c_g] + tabC_s[ch * 256 + c_g], 0.f);
                        float v1 = fmaxf(acc[mi][nj][2 * hh + 1] + tabA_s[c_g + 1] + tabC_s[ch * 256 + c_g + 1], 0.f);
                        u32 o = swoff(r_l, c_l >> 3) + (c_l & 7) * 2;
                        *(u32*)&smem[dst + o] = f2h(v0) | (f2h(v1) << 16);
                    }
                }
        }
        CP_WAIT0();
        __syncthreads();   // S4: h1 + W2 visible

        // ---- G34: L2 K=256 = h1c0(RB) x W2a(RW0) + h1c1(RA) x W2b(RW1) ----
        ZERO_ACC4();
        wg32s(sb + RB, sb + RW0, m0w, n0w32, lane, acc);
        wg32s(sb + RA, sb + RW1, m0w, n0w32, lane, acc);
        __syncthreads();   // S5: all regions free

        // C3: W3 -> RW0, W4 -> RW1 (under epi2)
        FILL_W(RW0, g_w3t, 128, 0);
        FILL_W(RW1, g_w4t, 128, 0);
        CP_COMMIT();
        // epi2: h2 -> RB
#define ACTEXPR2(v, r, c) fmaxf((v) + bs2[(c)], 0.f)
        EPI_SMEM4(RB, ACTEXPR2);
        CP_WAIT0();
        __syncthreads();   // S6: h2 + W3/W4 visible

        // ---- G5: L3 = h2(RB) x W3(RW0) ; epi3 (h3) -> RA ----
        ZERO_ACC4();
        wg32s(sb + RB, sb + RW0, m0w, n0w32, lane, acc);
#define ACTEXPR3(v, r, c) fmaxf((v) + bs3[(c)], 0.f)
        EPI_SMEM4(RA, ACTEXPR3);
        __syncthreads();   // S7: h3 visible

        // ---- G6: L4 = h3(RA) x W4(RW1) ; final epilogue -> gmem ----
        ZERO_ACC4();
        wg32s(sb + RA, sb + RW1, m0w, n0w32, lane, acc);

#pragma unroll
        for (int mi = 0; mi < 2; mi++)
#pragma unroll
            for (int nj = 0; nj < 4; nj++) {
                int c_l = n0w32 + nj * 8 + (lane & 3) * 2;
                float bb0 = bs4[c_l], bb1 = bs4[c_l + 1];
#pragma unroll
                for (int hh = 0; hh < 2; hh++) {
                    int r_l = m0w + mi * 16 + (lane >> 2) + hh * 8;
                    int tok = toks_s[r_l];
                    if (tok >= 0) {
                        float2 v;
                        v.x = acc[mi][nj][2 * hh] + bb0;
                        v.y = acc[mi][nj][2 * hh + 1] + bb1;
                        *(float2*)(out + (size_t)tok * 128 + c_l) = v;
                    }
                }
            }
    }
}

// ---------------- host ----------------
extern "C" void kernel_launch(void* const* d_in, const int* in_sizes, int n_in,
                              void* d_out, int out_size) {
    const int* seq = (const int*)d_in[0];
    const float* xyz = (const float*)d_in[1];
    const float* dih = (const float*)d_in[2];
    const int* cidx = (const int*)d_in[3];
    const float* ori = (const float*)d_in[4];
    const float* aa_emb = (const float*)d_in[6];
    const float* chain_emb = (const float*)d_in[7];
    const float* W1 = (const float*)d_in[8];
    const float* b1 = (const float*)d_in[9];
    const float* W2 = (const float*)d_in[10];
    const float* b2 = (const float*)d_in[11];
    const float* W3 = (const float*)d_in[12];
    const float* b3 = (const float*)d_in[13];
    const float* W4 = (const float*)d_in[14];
    const float* b4 = (const float*)d_in[15];
    float* out = (float*)d_out;

    cudaFuncSetAttribute(k_main, cudaFuncAttributeMaxDynamicSharedMemorySize, SMEM_MAIN);

    k_prep<<<238, 256>>>(seq, aa_emb, chain_emb, W1, b1, W2, W3, W4);
    k_scatter2<<<32, 512>>>(seq);
    k_main<<<148, 512, SMEM_MAIN>>>(xyz, dih, cidx, ori, b2, b3, b4, out);
}

// round 17
// speedup vs baseline: 1.4060x; 1.0205x over previous
#include <cuda_runtime.h>
#include <cuda_fp16.h>
#include <math.h>
#include <stdint.h>

#define NTOK 16384
#define H1D 256
#define TT 20
#define OFF_COORD 128
#define OFF_DIH   1628
#define OFF_CHAIN 1667

typedef unsigned short u16;
typedef unsigned int   u32;

// ---------------- scratch (static device globals; no allocation) ----------------
__device__ float g_tabA[TT * H1D];
__device__ float g_tabC[10 * H1D];
__device__ int g_cnt[TT];
__device__ int g_off[TT + 1];
__device__ int g_perm[NTOK];
__device__ int g_bhist[32 * TT];
__device__ int g_tiles[256];
__device__ int g_ntiles;
// pre-converted weights (single fp16), transposed to [n][k]
__device__ u16 g_w1t[TT * 256 * 128];
__device__ u16 g_w2t[128 * 256];
__device__ u16 g_w3t[128 * 128];
__device__ u16 g_w4t[128 * 128];

__constant__ float c_freq[6] = {1.0f, 2.0f, 3.0f, 1.0f, 0.5f, 1.0f / 3.0f};

// ---------------- helpers ----------------
__device__ __forceinline__ u32 smem_u32(const void* p) {
    u32 a;
    asm("{ .reg .u64 t; cvta.to.shared.u64 t, %1; cvt.u32.u64 %0, t; }" : "=r"(a) : "l"(p));
    return a;
}
__device__ __forceinline__ u32 f2h(float x) {
    return (u32)__half_as_ushort(__float2half_rn(x));
}
// swizzled byte offset of 16B chunk c8 (0..15) in row r (rows of 128 fp16 = 256B)
__device__ __forceinline__ u32 swoff(int r, int c8) {
    return (u32)r * 256u + ((((u32)c8) & 8u) | ((((u32)c8) ^ (u32)r) & 7u)) * 16u;
}
__device__ __forceinline__ void ldsm_x4(u32 addr, u32 (&r)[4]) {
    asm volatile("ldmatrix.sync.aligned.m8n8.x4.shared.b16 {%0,%1,%2,%3}, [%4];"
        : "=r"(r[0]), "=r"(r[1]), "=r"(r[2]), "=r"(r[3]) : "r"(addr));
}
__device__ __forceinline__ void mma_f16(float (&d)[4], const u32 (&a)[4], u32 b0, u32 b1) {
    asm volatile("mma.sync.aligned.m16n8k16.row.col.f32.f16.f16.f32 "
        "{%0,%1,%2,%3}, {%4,%5,%6,%7}, {%8,%9}, {%0,%1,%2,%3};"
        : "+f"(d[0]), "+f"(d[1]), "+f"(d[2]), "+f"(d[3])
        : "r"(a[0]), "r"(a[1]), "r"(a[2]), "r"(a[3]), "r"(b0), "r"(b1));
}
__device__ __forceinline__ void cpa16(u32 s, const void* g) {
    asm volatile("cp.async.cg.shared.global [%0], [%1], 16;" :: "r"(s), "l"(g) : "memory");
}
#define CP_COMMIT() asm volatile("cp.async.commit_group;" ::: "memory")
#define CP_WAIT0()  asm volatile("cp.async.wait_group 0;" ::: "memory")

// single-term fp16: warp tile 32x32 over N=128
__device__ __forceinline__ void wg32s(u32 As, u32 Bs,
                                      int m0w, int n0w, int lane,
                                      float (&acc)[2][8][4]) {
    int arow = (lane & 7) + ((lane >> 3) & 1) * 8;
    int akoff8 = (lane >> 4);
    int brow = (lane & 7) + ((lane >> 4) & 1) * 8;
    int bkoff8 = ((lane >> 3) & 1);
#pragma unroll
    for (int kc = 0; kc < 8; kc++) {
        u32 aS[2][4], bS[2][4];
#pragma unroll
        for (int mi = 0; mi < 2; mi++) {
            u32 off = swoff(m0w + mi * 16 + arow, kc * 2 + akoff8);
            ldsm_x4(As + off, aS[mi]);
        }
#pragma unroll
        for (int np = 0; np < 2; np++) {
            u32 off = swoff(n0w + np * 16 + brow, kc * 2 + bkoff8);
            ldsm_x4(Bs + off, bS[np]);
        }
#pragma unroll
        for (int mi = 0; mi < 2; mi++)
#pragma unroll
            for (int nj = 0; nj < 4; nj++)
                mma_f16(acc[mi][nj], aS[mi],
                        bS[nj >> 1][(nj & 1) * 2], bS[nj >> 1][(nj & 1) * 2 + 1]);
    }
}

// single-term fp16: warp tile 32x64 (nj 0..7), B local region + local n offset
__device__ __forceinline__ void wg64s(u32 As, u32 Bs, int n0loc,
                                      int m0w, int lane,
                                      float (&acc)[2][8][4]) {
    int arow = (lane & 7) + ((lane >> 3) & 1) * 8;
    int akoff8 = (lane >> 4);
    int brow = (lane & 7) + ((lane >> 4) & 1) * 8;
    int bkoff8 = ((lane >> 3) & 1);
#pragma unroll
    for (int kc = 0; kc < 8; kc++) {
        u32 aS[2][4], bS[4][4];
#pragma unroll
        for (int mi = 0; mi < 2; mi++) {
            u32 off = swoff(m0w + mi * 16 + arow, kc * 2 + akoff8);
            ldsm_x4(As + off, aS[mi]);
        }
#pragma unroll
        for (int np = 0; np < 4; np++) {
            u32 off = swoff(n0loc + np * 16 + brow, kc * 2 + bkoff8);
            ldsm_x4(Bs + off, bS[np]);
        }
#pragma unroll
        for (int mi = 0; mi < 2; mi++)
#pragma unroll
            for (int nj = 0; nj < 8; nj++)
                mma_f16(acc[mi][nj], aS[mi],
                        bS[nj >> 1][(nj & 1) * 2], bS[nj >> 1][(nj & 1) * 2 + 1]);
    }
}

// ---------------- fused prep kernel (fine-grained: 16-col weight tiles) ----------------
// blocks [0,32): hist; [32,62): tables; [62,382): W1 (20 types x 16 ntiles);
// [382,398): W2 (2 kb x 8 nb); [398,406): W3; [406,414): W4
__global__ void __launch_bounds__(256)
k_prep(const int* __restrict__ seq, const float* __restrict__ aa_emb,
       const float* __restrict__ chain_emb, const float* __restrict__ W1,
       const float* __restrict__ b1, const float* __restrict__ W2,
       const float* __restrict__ W3, const float* __restrict__ W4) {
    int b = blockIdx.x, tid = threadIdx.x;
    if (b < 32) {
        __shared__ int h[TT];
        if (tid < TT) h[tid] = 0;
        __syncthreads();
        int base = b * 512;
        atomicAdd(&h[seq[base + tid]], 1);
        atomicAdd(&h[seq[base + 256 + tid]], 1);
        __syncthreads();
        if (tid < TT) g_bhist[b * TT + tid] = h[tid];
        return;
    }
    if (b < 62) {
        int r = b - 32, j = tid;
        float acc = 0.f;
        if (r < TT) {
            const float* e = aa_emb + r * 128;
#pragma unroll 8
            for (int k = 0; k < 128; k++) acc += e[k] * W1[k * H1D + j];
            g_tabA[r * H1D + j] = acc + b1[j];
        } else {
            int c = r - TT;
            if (c != 0) {
                const float* e = chain_emb + c * 128;
#pragma unroll 8
                for (int k = 0; k < 128; k++) acc += e[k] * W1[(OFF_CHAIN + k) * H1D + j];
            }
            g_tabC[c * H1D + j] = acc;
        }
        return;
    }
    // weight transpose-split: [128 k x 16 n] tile per block
    __shared__ float s[128][17];
    const float* src;
    u16* dh;
    int Kd, n0glob, kskip = 0, srcN, srcRow0 = 0;
    bool w1 = false;
    int t = 0;
    int b2 = b - 62;
    if (b2 < 320) {
        t = b2 >> 4;
        int nb = b2 & 15;
        w1 = true;
        src = W1; srcN = 256; n0glob = nb * 16;
        dh = g_w1t + (size_t)t * 256 * 128;
        Kd = 128;
    } else if (b2 < 336) {
        int q = b2 - 320;
        int kb = q >> 3, nb = q & 7;
        src = W2; srcN = 128; n0glob = nb * 16; srcRow0 = kb * 128; kskip = kb * 128;
        dh = g_w2t; Kd = 256;
    } else if (b2 < 344) {
        int nb = b2 - 336;
        src = W3; srcN = 128; n0glob = nb * 16;
        dh = g_w3t; Kd = 128;
    } else {
        int nb = b2 - 344;
        src = W4; srcN = 128; n0glob = nb * 16;
        dh = g_w4t; Kd = 128;
    }
    // load 128k x 16n (coalesced over n, 16 threads per k-row)
#pragma unroll
    for (int it = 0; it < 8; it++) {
        int idx = tid + it * 256;
        int k = idx >> 4, nn = idx & 15;
        float v;
        if (w1) {
            if (k < 75) v = src[(size_t)(OFF_COORD + t * 75 + k) * srcN + n0glob + nn];
            else if (k < 114) v = src[(size_t)(OFF_DIH + k - 75) * srcN + n0glob + nn];
            else v = 0.f;
        } else {
            v = src[(size_t)(srcRow0 + k) * srcN + n0glob + nn];
        }
        s[k][nn] = v;
    }
    __syncthreads();
    // write transposed [n][k] as packed u32 (2 k per store)
#pragma unroll
    for (int it = 0; it < 4; it++) {
        int idx = tid + it * 256;
        int n = idx >> 6, kk = (idx & 63) * 2;
        u32 h0 = f2h(s[kk][n]);
        u32 h1 = f2h(s[kk + 1][n]);
        size_t o = (size_t)(n0glob + n) * Kd + kskip + kk;
        *(u32*)(dh + o) = h0 | (h1 << 16);
    }
}

// ---------------- scatter (scan folded in; block 0 publishes tile table) ----------------
__global__ void __launch_bounds__(512)
k_scatter2(const int* __restrict__ seq) {
    __shared__ int bh[32][TT];
    __shared__ int cnt[TT];
    __shared__ int off[TT + 1];
    __shared__ int cur[TT];
    __shared__ int pref[TT];
    int tid = threadIdx.x, b = blockIdx.x;
    for (int i = tid; i < 32 * TT; i += 512) bh[i / TT][i % TT] = g_bhist[i];
    __syncthreads();
    if (tid < TT) {
        int run = 0, mypref = 0;
#pragma unroll
        for (int s = 0; s < 32; s++) {
            if (s == b) mypref = run;
            run += bh[s][tid];
        }
        cnt[tid] = run;
        pref[tid] = mypref;
    }
    __syncthreads();
    if (tid == 0) {
        int o = 0;
        for (int t = 0; t < TT; t++) { off[t] = o; o += cnt[t]; }
        off[TT] = o;
    }
    __syncthreads();
    if (tid < TT) cur[tid] = off[tid] + pref[tid];
    if (b == 0) {
        if (tid < TT) { g_cnt[tid] = cnt[tid]; g_off[tid] = off[tid]; }
        if (tid == 0) {
            g_off[TT] = off[TT];
            int idx = 0;
            for (int t = 0; t < TT; t++)
                for (int tl = 0; tl * 128 < cnt[t]; tl++) g_tiles[idx++] = (t << 8) | tl;
            g_ntiles = idx;
        }
    }
    __syncthreads();
    int i = b * 512 + tid;
    int t = seq[i];
    int pos = atomicAdd(&cur[t], 1);
    g_perm[pos] = i;
}

// ---------------- fused main kernel (single-term fp16, 128-token tiles) ----------------
// RA, RB: 32KB activation regions (single fp16). RW0, RW1: 32KB weight regions.
#define RA  0
#define RB  32768
#define RW0 65536
#define RW1 98304
#define EX_TA   131072
#define EX_TC   132096
#define EX_B2   142336
#define EX_B3   142848
#define EX_B4   143360
#define EX_TOK  143872
#define EX_CH   144384
#define SMEM_MAIN 144896

__global__ void __launch_bounds__(512, 1)
k_main(const float* __restrict__ xyz, const float* __restrict__ dih,
       const int* __restrict__ cidx, const float* __restrict__ ori,
       const float* __restrict__ b2, const float* __restrict__ b3,
       const float* __restrict__ b4, float* __restrict__ out) {
    extern __shared__ char smem[];
    u32 sb = smem_u32(smem);
    int tid = threadIdx.x, wid = tid >> 5, lane = tid & 31;
    int* toks_s = (int*)(smem + EX_TOK);
    int* ch_s = (int*)(smem + EX_CH);
    float* tabA_s = (float*)(smem + EX_TA);
    float* tabC_s = (float*)(smem + EX_TC);
    float* bs2 = (float*)(smem + EX_B2);
    float* bs3 = (float*)(smem + EX_B3);
    float* bs4 = (float*)(smem + EX_B4);

    if (tid < 128) {
        bs2[tid] = b2[tid];
        bs3[tid] = b3[tid];
        bs4[tid] = b4[tid];
    }
    for (int i = tid; i < 2560; i += 512) tabC_s[i] = g_tabC[i];

    int m0w = (wid & 3) * 32;
    int n0w64 = (wid >> 2) * 64;
    int n0w32 = (wid >> 2) * 32;
    int r_fill = tid & 127;
    int c0_fill = (tid >> 7) * 4;
    int nt = g_ntiles;

#define FILL_W(DST, SRC, STRIDE, KOFF) do { \
        const uint4* _s = (const uint4*)((SRC) + (size_t)r_fill * (STRIDE) + (KOFF)); \
        _Pragma("unroll") \
        for (int i = 0; i < 4; i++) { \
            u32 o = swoff(r_fill, c0_fill + i); \
            cpa16(sb + (DST) + o, _s + c0_fill + i); \
        } \
    } while (0)

#define ZERO_ACC8() do { \
        _Pragma("unroll") for (int _a = 0; _a < 2; _a++) \
        _Pragma("unroll") for (int _b = 0; _b < 8; _b++) \
        _Pragma("unroll") for (int _c = 0; _c < 4; _c++) acc[_a][_b][_c] = 0.f; \
    } while (0)

#define ZERO_ACC4() do { \
        _Pragma("unroll") for (int _a = 0; _a < 2; _a++) \
        _Pragma("unroll") for (int _b = 0; _b < 4; _b++) \
        _Pragma("unroll") for (int _c = 0; _c < 4; _c++) acc[_a][_b][_c] = 0.f; \
    } while (0)

// epilogue for N=128 phases (nj 0..3) into a single fp16 region
#define EPI_SMEM4(DST, EXPR) do { \
        _Pragma("unroll") \
        for (int mi = 0; mi < 2; mi++) \
        _Pragma("unroll") \
        for (int nj = 0; nj < 4; nj++) { \
            int c_l = n0w32 + nj * 8 + (lane & 3) * 2; \
            _Pragma("unroll") \
            for (int hh = 0; hh < 2; hh++) { \
                int r_l = m0w + mi * 16 + (lane >> 2) + hh * 8; \
                float v0 = (EXPR(acc[mi][nj][2 * hh], r_l, c_l)); \
                float v1 = (EXPR(acc[mi][nj][2 * hh + 1], r_l, (c_l + 1))); \
                u32 o = swoff(r_l, c_l >> 3) + (c_l & 7) * 2; \
                *(u32*)&smem[(DST) + o] = f2h(v0) | (f2h(v1) << 16); \
            } \
        } \
    } while (0)

    for (int w = blockIdx.x; w < nt; w += gridDim.x) {
        int e = g_tiles[w];
        int type = e >> 8;
        int tile = e & 255;
        int cnt = g_cnt[type];
        int start = g_off[type] + tile * 128;
        int n = min(128, cnt - tile * 128);

        __syncthreads();   // S0: previous tile fully done
        if (tid < 128) {
            int tok = (tid < n) ? g_perm[start + tid] : -1;
            toks_s[tid] = tok;
            ch_s[tid] = (tok >= 0) ? cidx[tok] : 0;
        }
        for (int i = tid; i < 256; i += 512) tabA_s[i] = g_tabA[type * H1D + i];
        // C1: W1a -> RW0, W1b -> RW1 (under feature phase)
        FILL_W(RW0, g_w1t + (size_t)type * 256 * 128, 128, 0);
        FILL_W(RW1, g_w1t + (size_t)(type * 256 + 128) * 128, 128, 0);
        CP_COMMIT();
        __syncthreads();   // S1: toks visible

        // ---- features -> RA (single fp16) ----
        {
#pragma unroll 1
            for (int ti = 0; ti < 8; ti++) {
                int t = wid * 8 + ti;
                int tok = toks_s[t];
                const float* xb = xyz + (size_t)(tok < 0 ? 0 : tok) * 75;
                const float* ob = ori + (size_t)(tok < 0 ? 0 : tok) * 9;
                float cax = 0.f, cay = 0.f, caz = 0.f, d0 = 0.f, d1 = 0.f, d2 = 0.f;
                if (tok >= 0) {
                    cax = xb[3]; cay = xb[4]; caz = xb[5];
                    d0 = dih[(size_t)tok * 3]; d1 = dih[(size_t)tok * 3 + 1]; d2 = dih[(size_t)tok * 3 + 2];
                }
#pragma unroll
                for (int i = 0; i < 4; i++) {
                    int k = i * 32 + lane;
                    float v = 0.f;
                    if (tok >= 0) {
                        if (k < 75) {
                            int a = k / 3, c = k - a * 3;
                            float r0 = xb[a * 3 + 0] - cax;
                            float r1 = xb[a * 3 + 1] - cay;
                            float r2 = xb[a * 3 + 2] - caz;
                            v = ob[c] * r0 + ob[3 + c] * r1 + ob[6 + c] * r2;
                        } else if (k < 114) {
                            int kd = k - 75;
                            int dm = kd / 13, q = kd - dm * 13;
                            float x = (dm == 0) ? d0 : (dm == 1) ? d1 : d2;
                            if (q == 0) v = x;
                            else if (q <= 6) v = __sinf(c_freq[q - 1] * x);
                            else v = __cosf(c_freq[q - 7] * x);
                        }
                    }
                    u32 o = swoff(t, k >> 3) + (k & 7) * 2;
                    *(u16*)&smem[RA + o] = (u16)f2h(v);
                }
            }
        }
        CP_WAIT0();
        __syncthreads();   // S2: features + W1 visible

        float acc[2][8][4];

        // ---- G12: L1 full N=256 = feat(RA) x [W1a(RW0) | W1b(RW1)] ----
        ZERO_ACC8();
        {
            u32 Bs = (n0w64 < 128) ? (sb + RW0) : (sb + RW1);
            wg64s(sb + RA, Bs, n0w64 & 127, m0w, lane, acc);
        }
        __syncthreads();   // S3: RW0/RW1/RB free; RA (feat) dead after epi writes

        // C2: W2a -> RW0, W2b -> RW1 (under epilogue)
        FILL_W(RW0, g_w2t, 256, 0);
        FILL_W(RW1, g_w2t, 256, 128);
        CP_COMMIT();

        // epi01: h1 cols<128 -> RB, cols>=128 -> RA
        {
            int dst = (n0w64 < 128) ? RB : RA;
#pragma unroll
            for (int mi = 0; mi < 2; mi++)
#pragma unroll
                for (int nj = 0; nj < 8; nj++) {
                    int c_g = n0w64 + nj * 8 + (lane & 3) * 2;
                    int c_l = c_g & 127;
#pragma unroll
                    for (int hh = 0; hh < 2; hh++) {
                        int r_l = m0w + mi * 16 + (lane >> 2) + hh * 8;
                        int ch = ch_s[r_l];
                        float v0 = fmaxf(acc[mi][nj][2 * hh] + tabA_s[c_g] + tabC_s[ch * 256 + c_g], 0.f);
                        float v1 = fmaxf(acc[mi][nj][2 * hh + 1] + tabA_s[c_g + 1] + tabC_s[ch * 256 + c_g + 1], 0.f);
                        u32 o = swoff(r_l, c_l >> 3) + (c_l & 7) * 2;
                        *(u32*)&smem[dst + o] = f2h(v0) | (f2h(v1) << 16);
                    }
                }
        }
        CP_WAIT0();
        __syncthreads();   // S4: h1 + W2 visible

        // ---- G34: L2 K=256 = h1c0(RB) x W2a(RW0) + h1c1(RA) x W2b(RW1) ----
        ZERO_ACC4();
        wg32s(sb + RB, sb + RW0, m0w, n0w32, lane, acc);
        wg32s(sb + RA, sb + RW1, m0w, n0w32, lane, acc);
        __syncthreads();   // S5: all regions free

        // C3: W3 -> RW0, W4 -> RW1 (under epi2)
        FILL_W(RW0, g_w3t, 128, 0);
        FILL_W(RW1, g_w4t, 128, 0);
        CP_COMMIT();
        // epi2: h2 -> RB
#define ACTEXPR2(v, r, c) fmaxf((v) + bs2[(c)], 0.f)
        EPI_SMEM4(RB, ACTEXPR2);
        CP_WAIT0();
        __syncthreads();   // S6: h2 + W3/W4 visible

        // ---- G5: L3 = h2(RB) x W3(RW0) ; epi3 (h3) -> RA ----
        ZERO_ACC4();
        wg32s(sb + RB, sb + RW0, m0w, n0w32, lane, acc);
#define ACTEXPR3(v, r, c) fmaxf((v) + bs3[(c)], 0.f)
        EPI_SMEM4(RA, ACTEXPR3);
        __syncthreads();   // S7: h3 visible

        // ---- G6: L4 = h3(RA) x W4(RW1) ; final epilogue -> gmem ----
        ZERO_ACC4();
        wg32s(sb + RA, sb + RW1, m0w, n0w32, lane, acc);

#pragma unroll
        for (int mi = 0; mi < 2; mi++)
#pragma unroll
            for (int nj = 0; nj < 4; nj++) {
                int c_l = n0w32 + nj * 8 + (lane & 3) * 2;
                float bb0 = bs4[c_l], bb1 = bs4[c_l + 1];
#pragma unroll
                for (int hh = 0; hh < 2; hh++) {
                    int r_l = m0w + mi * 16 + (lane >> 2) + hh * 8;
                    int tok = toks_s[r_l];
                    if (tok >= 0) {
                        float2 v;
                        v.x = acc[mi][nj][2 * hh] + bb0;
                        v.y = acc[mi][nj][2 * hh + 1] + bb1;
                        *(float2*)(out + (size_t)tok * 128 + c_l) = v;
                    }
                }
            }
    }
}

// ---------------- host ----------------
extern "C" void kernel_launch(void* const* d_in, const int* in_sizes, int n_in,
                              void* d_out, int out_size) {
    const int* seq = (const int*)d_in[0];
    const float* xyz = (const float*)d_in[1];
    const float* dih = (const float*)d_in[2];
    const int* cidx = (const int*)d_in[3];
    const float* ori = (const float*)d_in[4];
    const float* aa_emb = (const float*)d_in[6];
    const float* chain_emb = (const float*)d_in[7];
    const float* W1 = (const float*)d_in[8];
    const float* b1 = (const float*)d_in[9];
    const float* W2 = (const float*)d_in[10];
    const float* b2 = (const float*)d_in[11];
    const float* W3 = (const float*)d_in[12];
    const float* b3 = (const float*)d_in[13];
    const float* W4 = (const float*)d_in[14];
    const float* b4 = (const float*)d_in[15];
    float* out = (float*)d_out;

    cudaFuncSetAttribute(k_main, cudaFuncAttributeMaxDynamicSharedMemorySize, SMEM_MAIN);

    k_prep<<<414, 256>>>(seq, aa_emb, chain_emb, W1, b1, W2, W3, W4);
    k_scatter2<<<32, 512>>>(seq);
    k_main<<<148, 512, SMEM_MAIN>>>(xyz, dih, cidx, ori, b2, b3, b4, out);
}